// round 2
// baseline (speedup 1.0000x reference)
#include <cuda_runtime.h>
#include <cstdint>

#define BB 2048
#define NN 50000
#define DD 128
#define DIN 256

#define TM 128
#define TN 128
#define SPLITS 18
#define NTILES ((NN + TN - 1) / TN)                 /* 391 */
#define TILES_PER ((NTILES + SPLITS - 1) / SPLITS)  /* 22  */

__device__ float g_y[BB * DD];                  // pre-BN activations
__device__ float g_h[BB * DD];                  // post-MLP hidden
__device__ unsigned long long g_best[BB];       // packed (ordered_score, ~idx)

// ---------------------------------------------------------------- utilities

__device__ __forceinline__ unsigned rotl32(unsigned v, int d) {
    return __funnelshift_l(v, v, d);
}

// JAX threefry2x32 with key = (0, 42)  (jax.random.key(42))
__device__ __forceinline__ uint2 threefry_0_42(unsigned c0, unsigned c1) {
    const unsigned ks0 = 0u, ks1 = 42u, ks2 = 0x1BD11BDAu ^ 0u ^ 42u;
    unsigned x0 = c0 + ks0;
    unsigned x1 = c1 + ks1;
#define TF_R(rot) { x0 += x1; x1 = rotl32(x1, rot); x1 ^= x0; }
    TF_R(13) TF_R(15) TF_R(26) TF_R(6)   x0 += ks1; x1 += ks2 + 1u;
    TF_R(17) TF_R(29) TF_R(16) TF_R(24)  x0 += ks2; x1 += ks0 + 2u;
    TF_R(13) TF_R(15) TF_R(26) TF_R(6)   x0 += ks0; x1 += ks1 + 3u;
    TF_R(17) TF_R(29) TF_R(16) TF_R(24)  x0 += ks1; x1 += ks2 + 4u;
    TF_R(13) TF_R(15) TF_R(26) TF_R(6)   x0 += ks2; x1 += ks0 + 5u;
#undef TF_R
    return make_uint2(x0, x1);
}

// jax_threefry_partitionable=True path: 32-bit random bits for linear index i
// (i < 2^32 here, so the 64-bit counter's hi word is 0):
//   bits = x0 ^ x1 of threefry(key, (0, i))
__device__ __forceinline__ unsigned jax_bits(unsigned i) {
    uint2 r = threefry_0_42(0u, i);
    return r.x ^ r.y;
}

// Matches jax.random.uniform(minval=tiny) + gumbel transform; logf is the
// accurate CUDA logf == libdevice __nv_logf (what XLA-GPU lowers log to).
__device__ __forceinline__ float gumbel_bits(unsigned bits) {
    float f = __uint_as_float((bits >> 9) | 0x3f800000u) - 1.0f;
    float u = fmaxf(f, 1.17549435e-38f);
    return -logf(-logf(u));
}

// Monotone pack: bigger score wins; on exact tie, SMALLER index wins
// (matches jnp.argmax first-occurrence semantics).
__device__ __forceinline__ unsigned long long pack_key(float z, unsigned c) {
    unsigned zu = __float_as_uint(z);
    zu = (zu & 0x80000000u) ? ~zu : (zu | 0x80000000u);
    return ((unsigned long long)zu << 32) | (unsigned)(~c);
}

__device__ __forceinline__ float blockReduceSum(float v, float* sbuf) {
    __syncthreads();   // protect sbuf reuse across calls
    int lane = threadIdx.x & 31, w = threadIdx.x >> 5;
    #pragma unroll
    for (int o = 16; o > 0; o >>= 1) v += __shfl_xor_sync(0xffffffffu, v, o);
    if (lane == 0) sbuf[w] = v;
    __syncthreads();
    float t = 0.f;
    int nw = blockDim.x >> 5;
    for (int i = 0; i < nw; i++) t += sbuf[i];
    return t;
}

// ---------------------------------------------------------------- kernels

__global__ void k_init(float* out, int out_size) {
    int i = blockIdx.x * 256 + threadIdx.x;
    if (i < BB) g_best[i] = 0ull;
    if (i < out_size) out[i] = 0.f;
}

// y = x @ W + b   (2048 x 256) @ (256 x 128)
__global__ __launch_bounds__(128) void k_mlp(const float* __restrict__ x,
                                             const float* __restrict__ W,
                                             const float* __restrict__ b) {
    __shared__ float xs[16][DIN];
    int r0 = blockIdx.x * 16;
    for (int i = threadIdx.x; i < 16 * DIN / 4; i += 128)
        ((float4*)xs)[i] = ((const float4*)(x + (size_t)r0 * DIN))[i];
    __syncthreads();
    int col = threadIdx.x;
    float acc[16];
    float bias = b[col];
    #pragma unroll
    for (int r = 0; r < 16; r++) acc[r] = bias;
    for (int k = 0; k < DIN; k += 4) {
        float w0 = W[(k + 0) * DD + col];
        float w1 = W[(k + 1) * DD + col];
        float w2 = W[(k + 2) * DD + col];
        float w3 = W[(k + 3) * DD + col];
        #pragma unroll
        for (int r = 0; r < 16; r++) {
            float4 xv = *(const float4*)&xs[r][k];
            acc[r] = fmaf(xv.x, w0, acc[r]);
            acc[r] = fmaf(xv.y, w1, acc[r]);
            acc[r] = fmaf(xv.z, w2, acc[r]);
            acc[r] = fmaf(xv.w, w3, acc[r]);
        }
    }
    #pragma unroll
    for (int r = 0; r < 16; r++)
        g_y[(size_t)(r0 + r) * DD + col] = acc[r];
}

// BatchNorm over axis 0 + LeakyReLU -> g_h. One block per output column.
__global__ __launch_bounds__(256) void k_bn(const float* __restrict__ gamma,
                                            const float* __restrict__ beta) {
    __shared__ float sbuf[8];
    int col = blockIdx.x;
    int tid = threadIdx.x;
    float v[8];
    float s = 0.f;
    #pragma unroll
    for (int i = 0; i < 8; i++) {
        v[i] = g_y[(size_t)(i * 256 + tid) * DD + col];
        s += v[i];
    }
    s = blockReduceSum(s, sbuf);
    float mean = s * (1.0f / BB);
    float s2 = 0.f;
    #pragma unroll
    for (int i = 0; i < 8; i++) { float d = v[i] - mean; s2 += d * d; }
    s2 = blockReduceSum(s2, sbuf);
    float var = s2 * (1.0f / BB);
    float rstd = 1.0f / sqrtf(var + 1e-5f);
    float ga = gamma[col], be = beta[col];
    #pragma unroll
    for (int i = 0; i < 8; i++) {
        float h = (v[i] - mean) * rstd * ga + be;
        h = (h >= 0.f) ? h : 0.01f * h;
        g_h[(size_t)(i * 256 + tid) * DD + col] = h;
    }
}

// Fused scores GEMM + exact JAX (partitionable-threefry) gumbel + per-row argmax.
// Block tile: 128 rows x 128 items; thread microtile 8x8.
__global__ __launch_bounds__(256, 1) void k_score(const float* __restrict__ A) {
    extern __shared__ float smem[];
    float* sh_h = smem;             // [k][row]  k-major, 64 KB
    float* sh_a = smem + DD * TM;   // [k][item] k-major, 64 KB

    int gy = blockIdx.y;            // 0..15  row group (rows gy*128 .. +127)
    int sp = blockIdx.x;            // 0..SPLITS-1 item split
    int tid = threadIdx.x;
    int ty = tid >> 4, tx = tid & 15;

    // load h tile transposed (once per block)
    {
        int i = tid >> 1;
        int kh = (tid & 1) * 64;
        const float4* src = (const float4*)(g_h + (size_t)(gy * TM + i) * DD + kh);
        #pragma unroll
        for (int q = 0; q < 16; q++) {
            float4 v4 = src[q];
            int k = kh + q * 4;
            sh_h[(k + 0) * TM + i] = v4.x;
            sh_h[(k + 1) * TM + i] = v4.y;
            sh_h[(k + 2) * TM + i] = v4.z;
            sh_h[(k + 3) * TM + i] = v4.w;
        }
    }

    unsigned long long best[8];
    #pragma unroll
    for (int p = 0; p < 8; p++) best[p] = 0ull;

    int t0 = sp * TILES_PER;
    int t1 = min(NTILES, t0 + TILES_PER);

    for (int t = t0; t < t1; t++) {
        int cbase = t * TN;
        __syncthreads();
        {   // load A tile transposed
            int i = tid >> 1;
            int kh = (tid & 1) * 64;
            int c = cbase + i;
            if (c < NN) {
                const float4* src = (const float4*)(A + (size_t)c * DD + kh);
                #pragma unroll
                for (int q = 0; q < 16; q++) {
                    float4 v4 = src[q];
                    int k = kh + q * 4;
                    sh_a[(k + 0) * TN + i] = v4.x;
                    sh_a[(k + 1) * TN + i] = v4.y;
                    sh_a[(k + 2) * TN + i] = v4.z;
                    sh_a[(k + 3) * TN + i] = v4.w;
                }
            } else {
                #pragma unroll
                for (int q = 0; q < 16; q++) {
                    int k = kh + q * 4;
                    sh_a[(k + 0) * TN + i] = 0.f;
                    sh_a[(k + 1) * TN + i] = 0.f;
                    sh_a[(k + 2) * TN + i] = 0.f;
                    sh_a[(k + 3) * TN + i] = 0.f;
                }
            }
        }
        __syncthreads();

        float acc[8][8];
        #pragma unroll
        for (int p = 0; p < 8; p++)
            #pragma unroll
            for (int j = 0; j < 8; j++) acc[p][j] = 0.f;

        #pragma unroll 8
        for (int k = 0; k < DD; k++) {
            float4 h0 = *(const float4*)&sh_h[k * TM + ty * 8];
            float4 h1 = *(const float4*)&sh_h[k * TM + ty * 8 + 4];
            float4 a0 = *(const float4*)&sh_a[k * TN + tx * 8];
            float4 a1 = *(const float4*)&sh_a[k * TN + tx * 8 + 4];
            float hv[8] = {h0.x, h0.y, h0.z, h0.w, h1.x, h1.y, h1.z, h1.w};
            float av[8] = {a0.x, a0.y, a0.z, a0.w, a1.x, a1.y, a1.z, a1.w};
            #pragma unroll
            for (int p = 0; p < 8; p++)
                #pragma unroll
                for (int j = 0; j < 8; j++)
                    acc[p][j] = fmaf(hv[p], av[j], acc[p][j]);
        }

        // gumbel + argmax update (partitionable threefry: 1 hash / element)
        #pragma unroll
        for (int j = 0; j < 8; j++) {
            unsigned c = (unsigned)(cbase + tx * 8 + j);
            if (c < (unsigned)NN) {
                unsigned ibase = (unsigned)(gy * TM + ty * 8) * (unsigned)NN + c;
                #pragma unroll
                for (int p = 0; p < 8; p++) {
                    unsigned bits = jax_bits(ibase + (unsigned)p * (unsigned)NN);
                    float z = acc[p][j] + gumbel_bits(bits);
                    unsigned long long key = pack_key(z, c);
                    if (key > best[p]) best[p] = key;
                }
            }
        }
    }

    #pragma unroll
    for (int p = 0; p < 8; p++) {
        int grow = gy * TM + ty * 8 + p;
        atomicMax(&g_best[grow], best[p]);
    }
}

// Unpack argmax, cosine similarity, reductions, write outputs.
__global__ __launch_bounds__(256) void k_final(const float* __restrict__ A,
                                               const int* __restrict__ uid,
                                               float* out, int out_size) {
    __shared__ float sbuf[8];
    int tid = threadIdx.x;
    float sl = 0.f, sm = 0.f;
    for (int r = tid; r < BB; r += 256) {
        unsigned c = ~((unsigned)(g_best[r] & 0xffffffffull));
        if (r < out_size) out[r] = (float)c;
        const float* orig = A + (size_t)uid[2 * r + 1] * DD;
        const float* rep  = A + (size_t)c * DD;
        float dot = 0.f, n1 = 0.f, n2 = 0.f;
        #pragma unroll 4
        for (int k = 0; k < DD; k++) {
            float a = orig[k], b2 = rep[k];
            dot = fmaf(a, b2, dot);
            n1  = fmaf(a, a, n1);
            n2  = fmaf(b2, b2, n2);
        }
        n1 = fmaxf(sqrtf(n1), 1e-6f);
        n2 = fmaxf(sqrtf(n2), 1e-6f);
        float sim = dot / (n1 * n2);
        sim = (sim + 1.f) * 0.5f;
        float d = sim - 0.5f;   // labels = SIM_RATIO = 0.5
        sl += d * d;
        sm += sim;
    }
    sl = blockReduceSum(sl, sbuf);
    sm = blockReduceSum(sm, sbuf);
    if (tid == 0 && out_size >= 2050) {
        out[2048] = sl * (1.0f / BB);
        out[2049] = sm * (1.0f / BB);
    }
}

// ---------------------------------------------------------------- launcher

extern "C" void kernel_launch(void* const* d_in, const int* in_sizes, int n_in,
                              void* d_out, int out_size) {
    const int*   uid   = (const int*)d_in[0];    // user_item_id [2048,2] int32
    const float* x     = (const float*)d_in[1];  // item_feature [2048,256]
    const float* A     = (const float*)d_in[2];  // all_items [50000,128]
    const float* W     = (const float*)d_in[3];  // W [256,128]
    const float* b     = (const float*)d_in[4];  // b [128]
    const float* gamma = (const float*)d_in[5];  // gamma [128]
    const float* beta  = (const float*)d_in[6];  // beta [128]
    float* out = (float*)d_out;

    (void)in_sizes; (void)n_in;

    size_t smem_bytes = (size_t)2 * DD * TM * sizeof(float);  // 128 KB
    cudaFuncSetAttribute(k_score, cudaFuncAttributeMaxDynamicSharedMemorySize,
                         (int)smem_bytes);

    int initN = out_size > BB ? out_size : BB;
    k_init<<<(initN + 255) / 256, 256>>>(out, out_size);
    k_mlp<<<BB / 16, 128>>>(x, W, b);
    k_bn<<<DD, 256>>>(gamma, beta);
    dim3 grid(SPLITS, 16);
    k_score<<<grid, 256, smem_bytes>>>(A);
    k_final<<<1, 256>>>(A, uid, out, out_size);
}

// round 3
// speedup vs baseline: 1.3172x; 1.3172x over previous
#include <cuda_runtime.h>
#include <cstdint>

#define BB 2048
#define NN 50000
#define DD 128
#define DIN 256

#define TM 128
#define TN 128
#define SPLITS 18
#define NTILES ((NN + TN - 1) / TN)                 /* 391 */
#define TILES_PER ((NTILES + SPLITS - 1) / SPLITS)  /* 22  */

#define GMAX 16.0f   /* strict upper bound on jax gumbel noise (max ~15.95) */

typedef unsigned long long u64;

__device__ float g_y[BB * DD];                  // pre-BN activations
__device__ float g_h[BB * DD];                  // post-MLP hidden
__device__ u64   g_best[BB];                    // packed (ordered_score, ~idx)
__device__ float g_ps[2][16];                   // partial sums for final reduce

// ---------------------------------------------------------------- utilities

__device__ __forceinline__ unsigned rotl32(unsigned v, int d) {
    return __funnelshift_l(v, v, d);
}

// JAX threefry2x32 with key = (0, 42)
__device__ __forceinline__ uint2 threefry_0_42(unsigned c0, unsigned c1) {
    const unsigned ks0 = 0u, ks1 = 42u, ks2 = 0x1BD11BDAu ^ 0u ^ 42u;
    unsigned x0 = c0 + ks0;
    unsigned x1 = c1 + ks1;
#define TF_R(rot) { x0 += x1; x1 = rotl32(x1, rot); x1 ^= x0; }
    TF_R(13) TF_R(15) TF_R(26) TF_R(6)   x0 += ks1; x1 += ks2 + 1u;
    TF_R(17) TF_R(29) TF_R(16) TF_R(24)  x0 += ks2; x1 += ks0 + 2u;
    TF_R(13) TF_R(15) TF_R(26) TF_R(6)   x0 += ks0; x1 += ks1 + 3u;
    TF_R(17) TF_R(29) TF_R(16) TF_R(24)  x0 += ks1; x1 += ks2 + 4u;
    TF_R(13) TF_R(15) TF_R(26) TF_R(6)   x0 += ks2; x1 += ks0 + 5u;
#undef TF_R
    return make_uint2(x0, x1);
}

// jax_threefry_partitionable path: bits(i) = x0 ^ x1 of threefry(key,(0,i))
__device__ __forceinline__ unsigned jax_bits(unsigned i) {
    uint2 r = threefry_0_42(0u, i);
    return r.x ^ r.y;
}

__device__ __forceinline__ float gumbel_bits(unsigned bits) {
    float f = __uint_as_float((bits >> 9) | 0x3f800000u) - 1.0f;
    float u = fmaxf(f, 1.17549435e-38f);
    return -logf(-logf(u));
}

// Monotone pack: bigger z wins; on exact tie, SMALLER index wins.
__device__ __forceinline__ u64 pack_key(float z, unsigned c) {
    unsigned zu = __float_as_uint(z);
    zu = (zu & 0x80000000u) ? ~zu : (zu | 0x80000000u);
    return ((u64)zu << 32) | (unsigned)(~c);
}

// ---- f32x2 packed-math helpers ----
__device__ __forceinline__ u64 pack_ff(float lo, float hi) {
    u64 v;
    asm("mov.b64 %0, {%1, %2};" : "=l"(v) : "f"(lo), "f"(hi));
    return v;
}
__device__ __forceinline__ void unpack_ff(u64 v, float& lo, float& hi) {
    asm("mov.b64 {%0, %1}, %2;" : "=f"(lo), "=f"(hi) : "l"(v));
}
__device__ __forceinline__ u64 ffma2(u64 a, u64 b, u64 c) {
    u64 d;
    asm("fma.rn.f32x2 %0, %1, %2, %3;" : "=l"(d) : "l"(a), "l"(b), "l"(c));
    return d;
}

__device__ __forceinline__ float blockReduceSum(float v, float* sbuf, int nthreads) {
    __syncthreads();
    int lane = threadIdx.x & 31, w = threadIdx.x >> 5;
    #pragma unroll
    for (int o = 16; o > 0; o >>= 1) v += __shfl_xor_sync(0xffffffffu, v, o);
    if (lane == 0) sbuf[w] = v;
    __syncthreads();
    float t = 0.f;
    int nw = nthreads >> 5;
    for (int i = 0; i < nw; i++) t += sbuf[i];
    return t;
}

// ---------------------------------------------------------------- kernels

__global__ void k_init(float* out, int out_size) {
    int i = blockIdx.x * 256 + threadIdx.x;
    if (i < BB) g_best[i] = 0ull;
    if (i < out_size) out[i] = 0.f;
}

// y = x @ W + b   (2048 x 256) @ (256 x 128)
__global__ __launch_bounds__(128) void k_mlp(const float* __restrict__ x,
                                             const float* __restrict__ W,
                                             const float* __restrict__ b) {
    __shared__ float xs[16][DIN];
    int r0 = blockIdx.x * 16;
    for (int i = threadIdx.x; i < 16 * DIN / 4; i += 128)
        ((float4*)xs)[i] = ((const float4*)(x + (size_t)r0 * DIN))[i];
    __syncthreads();
    int col = threadIdx.x;
    float acc[16];
    float bias = b[col];
    #pragma unroll
    for (int r = 0; r < 16; r++) acc[r] = bias;
    for (int k = 0; k < DIN; k += 4) {
        float w0 = W[(k + 0) * DD + col];
        float w1 = W[(k + 1) * DD + col];
        float w2 = W[(k + 2) * DD + col];
        float w3 = W[(k + 3) * DD + col];
        #pragma unroll
        for (int r = 0; r < 16; r++) {
            float4 xv = *(const float4*)&xs[r][k];
            acc[r] = fmaf(xv.x, w0, acc[r]);
            acc[r] = fmaf(xv.y, w1, acc[r]);
            acc[r] = fmaf(xv.z, w2, acc[r]);
            acc[r] = fmaf(xv.w, w3, acc[r]);
        }
    }
    #pragma unroll
    for (int r = 0; r < 16; r++)
        g_y[(size_t)(r0 + r) * DD + col] = acc[r];
}

// BatchNorm over axis 0 + LeakyReLU -> g_h. One block per output column.
__global__ __launch_bounds__(256) void k_bn(const float* __restrict__ gamma,
                                            const float* __restrict__ beta) {
    __shared__ float sbuf[8];
    int col = blockIdx.x;
    int tid = threadIdx.x;
    float v[8];
    float s = 0.f;
    #pragma unroll
    for (int i = 0; i < 8; i++) {
        v[i] = g_y[(size_t)(i * 256 + tid) * DD + col];
        s += v[i];
    }
    s = blockReduceSum(s, sbuf, 256);
    float mean = s * (1.0f / BB);
    float s2 = 0.f;
    #pragma unroll
    for (int i = 0; i < 8; i++) { float d = v[i] - mean; s2 += d * d; }
    s2 = blockReduceSum(s2, sbuf, 256);
    float var = s2 * (1.0f / BB);
    float rstd = 1.0f / sqrtf(var + 1e-5f);
    float ga = gamma[col], be = beta[col];
    #pragma unroll
    for (int i = 0; i < 8; i++) {
        float h = (v[i] - mean) * rstd * ga + be;
        h = (h >= 0.f) ? h : 0.01f * h;
        g_h[(size_t)(i * 256 + tid) * DD + col] = h;
    }
}

// Fused scores GEMM (f32x2-packed) + bounded-gumbel-filtered argmax.
// Block tile: 128 rows x 128 items; thread microtile 8x8 (as 8x4 f32x2 pairs).
__global__ __launch_bounds__(256, 1) void k_score(const float* __restrict__ A) {
    extern __shared__ float smem[];
    float* sh_h = smem;             // [k][row]  k-major, 64 KB
    float* sh_a = smem + DD * TM;   // [k][item] k-major, 64 KB

    int gy = blockIdx.y;            // 0..15  row group (rows gy*128 .. +127)
    int sp = blockIdx.x;            // 0..SPLITS-1 item split
    int tid = threadIdx.x;
    int ty = tid >> 4, tx = tid & 15;

    // load h tile transposed (once per block)
    {
        int i = tid >> 1;
        int kh = (tid & 1) * 64;
        const float4* src = (const float4*)(g_h + (size_t)(gy * TM + i) * DD + kh);
        #pragma unroll
        for (int q = 0; q < 16; q++) {
            float4 v4 = src[q];
            int k = kh + q * 4;
            sh_h[(k + 0) * TM + i] = v4.x;
            sh_h[(k + 1) * TM + i] = v4.y;
            sh_h[(k + 2) * TM + i] = v4.z;
            sh_h[(k + 3) * TM + i] = v4.w;
        }
    }

    u64 best[8];
    float zbest[8];
    #pragma unroll
    for (int p = 0; p < 8; p++) { best[p] = 0ull; zbest[p] = -__int_as_float(0x7f800000); }

    int t0 = sp * TILES_PER;
    int t1 = min(NTILES, t0 + TILES_PER);

    for (int t = t0; t < t1; t++) {
        int cbase = t * TN;
        __syncthreads();
        {   // load A tile transposed
            int i = tid >> 1;
            int kh = (tid & 1) * 64;
            int c = cbase + i;
            if (c < NN) {
                const float4* src = (const float4*)(A + (size_t)c * DD + kh);
                #pragma unroll
                for (int q = 0; q < 16; q++) {
                    float4 v4 = src[q];
                    int k = kh + q * 4;
                    sh_a[(k + 0) * TN + i] = v4.x;
                    sh_a[(k + 1) * TN + i] = v4.y;
                    sh_a[(k + 2) * TN + i] = v4.z;
                    sh_a[(k + 3) * TN + i] = v4.w;
                }
            } else {
                #pragma unroll
                for (int q = 0; q < 16; q++) {
                    int k = kh + q * 4;
                    sh_a[(k + 0) * TN + i] = 0.f;
                    sh_a[(k + 1) * TN + i] = 0.f;
                    sh_a[(k + 2) * TN + i] = 0.f;
                    sh_a[(k + 3) * TN + i] = 0.f;
                }
            }
        }
        __syncthreads();

        // ---- GEMM microtile: acc2[p][j2] holds cols (2*j2, 2*j2+1) packed
        u64 acc2[8][4];
        #pragma unroll
        for (int p = 0; p < 8; p++)
            #pragma unroll
            for (int j = 0; j < 4; j++) acc2[p][j] = 0ull;

        #pragma unroll 8
        for (int k = 0; k < DD; k++) {
            ulonglong2 a01 = *(const ulonglong2*)&sh_a[k * TN + tx * 8];
            ulonglong2 a23 = *(const ulonglong2*)&sh_a[k * TN + tx * 8 + 4];
            u64 av2[4] = {a01.x, a01.y, a23.x, a23.y};
            float4 h0 = *(const float4*)&sh_h[k * TM + ty * 8];
            float4 h1 = *(const float4*)&sh_h[k * TM + ty * 8 + 4];
            float hv[8] = {h0.x, h0.y, h0.z, h0.w, h1.x, h1.y, h1.z, h1.w};
            #pragma unroll
            for (int p = 0; p < 8; p++) {
                u64 hb = pack_ff(hv[p], hv[p]);
                #pragma unroll
                for (int j = 0; j < 4; j++)
                    acc2[p][j] = ffma2(hb, av2[j], acc2[p][j]);
            }
        }

        // ---- unpack + row maxes
        float accf[8][8];
        float rmax[8];
        #pragma unroll
        for (int p = 0; p < 8; p++) {
            #pragma unroll
            for (int j = 0; j < 4; j++)
                unpack_ff(acc2[p][j], accf[p][2 * j], accf[p][2 * j + 1]);
            float m = accf[p][0];
            #pragma unroll
            for (int j = 1; j < 8; j++) m = fmaxf(m, accf[p][j]);
            rmax[p] = m;
        }

        // ---- share zbest across the 16 lanes covering the same rows
        // (lanes 0-15 / 16-31 of each warp share ty). Collective: no divergence.
        #pragma unroll
        for (int p = 0; p < 8; p++) {
            float z = zbest[p];
            #pragma unroll
            for (int o = 8; o > 0; o >>= 1)
                z = fmaxf(z, __shfl_xor_sync(0xffffffffu, z, o, 16));
            zbest[p] = z;
        }

        // ---- bounded-gumbel filter: skip row if even max score + GMAX can't win
        #pragma unroll
        for (int p = 0; p < 8; p++) {
            if (rmax[p] + GMAX >= zbest[p]) {
                unsigned rbase = (unsigned)(gy * TM + ty * 8 + p) * (unsigned)NN;
                #pragma unroll
                for (int j = 0; j < 8; j++) {
                    unsigned c = (unsigned)(cbase + tx * 8 + j);
                    float a = accf[p][j];
                    if (c < (unsigned)NN && a + GMAX >= zbest[p]) {
                        float z = a + gumbel_bits(jax_bits(rbase + c));
                        u64 key = pack_key(z, c);
                        if (key > best[p]) best[p] = key;
                        zbest[p] = fmaxf(zbest[p], z);
                    }
                }
            }
        }
    }

    #pragma unroll
    for (int p = 0; p < 8; p++)
        atomicMax(&g_best[gy * TM + ty * 8 + p], best[p]);
}

// Unpack argmax, cosine similarity, partial reductions (16 blocks x 128 rows).
__global__ __launch_bounds__(128) void k_final(const float* __restrict__ A,
                                               const int* __restrict__ uid,
                                               float* out, int out_size) {
    __shared__ float sbuf[4];
    int tid = threadIdx.x;
    int r = blockIdx.x * 128 + tid;
    unsigned c = ~((unsigned)(g_best[r] & 0xffffffffull));
    if (r < out_size) out[r] = (float)c;
    const float* orig = A + (size_t)uid[2 * r + 1] * DD;
    const float* rep  = A + (size_t)c * DD;
    float dot = 0.f, n1 = 0.f, n2 = 0.f;
    #pragma unroll 4
    for (int k = 0; k < DD; k++) {
        float a = orig[k], b2 = rep[k];
        dot = fmaf(a, b2, dot);
        n1  = fmaf(a, a, n1);
        n2  = fmaf(b2, b2, n2);
    }
    n1 = fmaxf(sqrtf(n1), 1e-6f);
    n2 = fmaxf(sqrtf(n2), 1e-6f);
    float sim = dot / (n1 * n2);
    sim = (sim + 1.f) * 0.5f;
    float d = sim - 0.5f;   // labels = SIM_RATIO = 0.5
    float sl = blockReduceSum(d * d, sbuf, 128);
    float sm = blockReduceSum(sim, sbuf, 128);
    if (tid == 0) {
        g_ps[0][blockIdx.x] = sl;
        g_ps[1][blockIdx.x] = sm;
    }
}

__global__ void k_fin2(float* out, int out_size) {
    if (threadIdx.x == 0 && out_size >= 2050) {
        float sl = 0.f, sm = 0.f;
        for (int i = 0; i < 16; i++) { sl += g_ps[0][i]; sm += g_ps[1][i]; }
        out[2048] = sl * (1.0f / BB);
        out[2049] = sm * (1.0f / BB);
    }
}

// ---------------------------------------------------------------- launcher

extern "C" void kernel_launch(void* const* d_in, const int* in_sizes, int n_in,
                              void* d_out, int out_size) {
    const int*   uid   = (const int*)d_in[0];    // user_item_id [2048,2] int32
    const float* x     = (const float*)d_in[1];  // item_feature [2048,256]
    const float* A     = (const float*)d_in[2];  // all_items [50000,128]
    const float* W     = (const float*)d_in[3];  // W [256,128]
    const float* b     = (const float*)d_in[4];  // b [128]
    const float* gamma = (const float*)d_in[5];  // gamma [128]
    const float* beta  = (const float*)d_in[6];  // beta [128]
    float* out = (float*)d_out;

    (void)in_sizes; (void)n_in;

    size_t smem_bytes = (size_t)2 * DD * TM * sizeof(float);  // 128 KB
    cudaFuncSetAttribute(k_score, cudaFuncAttributeMaxDynamicSharedMemorySize,
                         (int)smem_bytes);

    int initN = out_size > BB ? out_size : BB;
    k_init<<<(initN + 255) / 256, 256>>>(out, out_size);
    k_mlp<<<BB / 16, 128>>>(x, W, b);
    k_bn<<<DD, 256>>>(gamma, beta);
    dim3 grid(SPLITS, 16);
    k_score<<<grid, 256, smem_bytes>>>(A);
    k_final<<<16, 128>>>(A, uid, out, out_size);
    k_fin2<<<1, 32>>>(out, out_size);
}

// round 4
// speedup vs baseline: 1.6943x; 1.2863x over previous
#include <cuda_runtime.h>
#include <cstdint>

#define BB 2048
#define NN 50000
#define DD 128
#define DIN 256

#define TM 128
#define TN 64
#define SPLITS 18
#define NTILES ((NN + TN - 1) / TN)                 /* 782 */
#define TILES_PER ((NTILES + SPLITS - 1) / SPLITS)  /* 44  */

#define GMAX 16.0f   /* strict upper bound on jax gumbel noise (max ~15.95) */

typedef unsigned long long u64;

__device__ float g_y[BB * DD];                  // pre-BN activations
__device__ float g_h[BB * DD];                  // post-MLP hidden
__device__ u64   g_best[BB];                    // packed (ordered_score, ~idx)
__device__ float g_ps[2][16];                   // partial sums for final reduce

// ---------------------------------------------------------------- utilities

__device__ __forceinline__ unsigned rotl32(unsigned v, int d) {
    return __funnelshift_l(v, v, d);
}

// JAX threefry2x32 with key = (0, 42)
__device__ __forceinline__ uint2 threefry_0_42(unsigned c0, unsigned c1) {
    const unsigned ks0 = 0u, ks1 = 42u, ks2 = 0x1BD11BDAu ^ 0u ^ 42u;
    unsigned x0 = c0 + ks0;
    unsigned x1 = c1 + ks1;
#define TF_R(rot) { x0 += x1; x1 = rotl32(x1, rot); x1 ^= x0; }
    TF_R(13) TF_R(15) TF_R(26) TF_R(6)   x0 += ks1; x1 += ks2 + 1u;
    TF_R(17) TF_R(29) TF_R(16) TF_R(24)  x0 += ks2; x1 += ks0 + 2u;
    TF_R(13) TF_R(15) TF_R(26) TF_R(6)   x0 += ks0; x1 += ks1 + 3u;
    TF_R(17) TF_R(29) TF_R(16) TF_R(24)  x0 += ks1; x1 += ks2 + 4u;
    TF_R(13) TF_R(15) TF_R(26) TF_R(6)   x0 += ks2; x1 += ks0 + 5u;
#undef TF_R
    return make_uint2(x0, x1);
}

// jax_threefry_partitionable path: bits(i) = x0 ^ x1 of threefry(key,(0,i))
__device__ __forceinline__ unsigned jax_bits(unsigned i) {
    uint2 r = threefry_0_42(0u, i);
    return r.x ^ r.y;
}

__device__ __forceinline__ float gumbel_bits(unsigned bits) {
    float f = __uint_as_float((bits >> 9) | 0x3f800000u) - 1.0f;
    float u = fmaxf(f, 1.17549435e-38f);
    return -logf(-logf(u));
}

// Monotone pack: bigger z wins; on exact tie, SMALLER index wins.
__device__ __forceinline__ u64 pack_key(float z, unsigned c) {
    unsigned zu = __float_as_uint(z);
    zu = (zu & 0x80000000u) ? ~zu : (zu | 0x80000000u);
    return ((u64)zu << 32) | (unsigned)(~c);
}

// ---- f32x2 packed-math helpers ----
__device__ __forceinline__ u64 pack_ff(float lo, float hi) {
    u64 v;
    asm("mov.b64 %0, {%1, %2};" : "=l"(v) : "f"(lo), "f"(hi));
    return v;
}
__device__ __forceinline__ void unpack_ff(u64 v, float& lo, float& hi) {
    asm("mov.b64 {%0, %1}, %2;" : "=f"(lo), "=f"(hi) : "l"(v));
}
__device__ __forceinline__ u64 ffma2(u64 a, u64 b, u64 c) {
    u64 d;
    asm("fma.rn.f32x2 %0, %1, %2, %3;" : "=l"(d) : "l"(a), "l"(b), "l"(c));
    return d;
}

__device__ __forceinline__ float blockReduceSum(float v, float* sbuf, int nthreads) {
    __syncthreads();
    int lane = threadIdx.x & 31, w = threadIdx.x >> 5;
    #pragma unroll
    for (int o = 16; o > 0; o >>= 1) v += __shfl_xor_sync(0xffffffffu, v, o);
    if (lane == 0) sbuf[w] = v;
    __syncthreads();
    float t = 0.f;
    int nw = nthreads >> 5;
    for (int i = 0; i < nw; i++) t += sbuf[i];
    return t;
}

// ---------------------------------------------------------------- kernels

__global__ void k_init(float* out, int out_size) {
    int i = blockIdx.x * 256 + threadIdx.x;
    if (i < BB) g_best[i] = 0ull;
    if (i < out_size) out[i] = 0.f;
}

// y = x @ W + b   (2048 x 256) @ (256 x 128)
__global__ __launch_bounds__(128) void k_mlp(const float* __restrict__ x,
                                             const float* __restrict__ W,
                                             const float* __restrict__ b) {
    __shared__ float xs[16][DIN];
    int r0 = blockIdx.x * 16;
    for (int i = threadIdx.x; i < 16 * DIN / 4; i += 128)
        ((float4*)xs)[i] = ((const float4*)(x + (size_t)r0 * DIN))[i];
    __syncthreads();
    int col = threadIdx.x;
    float acc[16];
    float bias = b[col];
    #pragma unroll
    for (int r = 0; r < 16; r++) acc[r] = bias;
    for (int k = 0; k < DIN; k += 4) {
        float w0 = W[(k + 0) * DD + col];
        float w1 = W[(k + 1) * DD + col];
        float w2 = W[(k + 2) * DD + col];
        float w3 = W[(k + 3) * DD + col];
        #pragma unroll
        for (int r = 0; r < 16; r++) {
            float4 xv = *(const float4*)&xs[r][k];
            acc[r] = fmaf(xv.x, w0, acc[r]);
            acc[r] = fmaf(xv.y, w1, acc[r]);
            acc[r] = fmaf(xv.z, w2, acc[r]);
            acc[r] = fmaf(xv.w, w3, acc[r]);
        }
    }
    #pragma unroll
    for (int r = 0; r < 16; r++)
        g_y[(size_t)(r0 + r) * DD + col] = acc[r];
}

// BatchNorm over axis 0 + LeakyReLU -> g_h. One block per output column.
__global__ __launch_bounds__(256) void k_bn(const float* __restrict__ gamma,
                                            const float* __restrict__ beta) {
    __shared__ float sbuf[8];
    int col = blockIdx.x;
    int tid = threadIdx.x;
    float v[8];
    float s = 0.f;
    #pragma unroll
    for (int i = 0; i < 8; i++) {
        v[i] = g_y[(size_t)(i * 256 + tid) * DD + col];
        s += v[i];
    }
    s = blockReduceSum(s, sbuf, 256);
    float mean = s * (1.0f / BB);
    float s2 = 0.f;
    #pragma unroll
    for (int i = 0; i < 8; i++) { float d = v[i] - mean; s2 += d * d; }
    s2 = blockReduceSum(s2, sbuf, 256);
    float var = s2 * (1.0f / BB);
    float rstd = 1.0f / sqrtf(var + 1e-5f);
    float ga = gamma[col], be = beta[col];
    #pragma unroll
    for (int i = 0; i < 8; i++) {
        float h = (v[i] - mean) * rstd * ga + be;
        h = (h >= 0.f) ? h : 0.01f * h;
        g_h[(size_t)(i * 256 + tid) * DD + col] = h;
    }
}

// Fused scores GEMM (f32x2, row-pair packed) + bounded-gumbel-filtered argmax.
// Block tile: 128 rows x 64 items; thread microtile 8 rows x 4 cols.
// smem 96KB -> 2 blocks/SM (16 warps, 4/SMSP).
__global__ __launch_bounds__(256, 2) void k_score(const float* __restrict__ A) {
    extern __shared__ float smem[];
    float* sh_h = smem;             // [k][row]  k-major 128x128, 64 KB
    float* sh_a = smem + DD * TM;   // [k][col]  k-major 128x64,  32 KB

    int gy = blockIdx.y;            // 0..15  row group (rows gy*128 .. +127)
    int sp = blockIdx.x;            // 0..SPLITS-1 item split
    int tid = threadIdx.x;
    int ty = tid >> 4, tx = tid & 15;

    // load h tile transposed: thread = (row = tid&127, k-half = tid>>7)
    {
        int row = tid & 127;
        int k0 = (tid >> 7) * 64;
        const float4* src = (const float4*)(g_h + (size_t)(gy * TM + row) * DD + k0);
        #pragma unroll
        for (int q = 0; q < 16; q++) {
            float4 v4 = src[q];
            int k = k0 + q * 4;
            sh_h[(k + 0) * TM + row] = v4.x;
            sh_h[(k + 1) * TM + row] = v4.y;
            sh_h[(k + 2) * TM + row] = v4.z;
            sh_h[(k + 3) * TM + row] = v4.w;
        }
    }

    u64 best[8];
    float zbest[8];
    #pragma unroll
    for (int p = 0; p < 8; p++) { best[p] = 0ull; zbest[p] = -__int_as_float(0x7f800000); }

    int t0 = sp * TILES_PER;
    int t1 = min(NTILES, t0 + TILES_PER);

    for (int t = t0; t < t1; t++) {
        int cbase = t * TN;
        __syncthreads();
        {   // load A tile transposed: thread = (col = tid&63, k-quarter = tid>>6)
            int col = tid & 63;
            int k0 = (tid >> 6) * 32;
            int c = cbase + col;
            if (c < NN) {
                const float4* src = (const float4*)(A + (size_t)c * DD + k0);
                #pragma unroll
                for (int q = 0; q < 8; q++) {
                    float4 v4 = src[q];
                    int k = k0 + q * 4;
                    sh_a[(k + 0) * TN + col] = v4.x;
                    sh_a[(k + 1) * TN + col] = v4.y;
                    sh_a[(k + 2) * TN + col] = v4.z;
                    sh_a[(k + 3) * TN + col] = v4.w;
                }
            } else {
                #pragma unroll
                for (int q = 0; q < 8; q++) {
                    int k = k0 + q * 4;
                    sh_a[(k + 0) * TN + col] = 0.f;
                    sh_a[(k + 1) * TN + col] = 0.f;
                    sh_a[(k + 2) * TN + col] = 0.f;
                    sh_a[(k + 3) * TN + col] = 0.f;
                }
            }
        }
        __syncthreads();

        // ---- GEMM microtile: acc2[p2][j] = rows (2p2, 2p2+1) packed, col j
        u64 acc2[4][4];
        #pragma unroll
        for (int p = 0; p < 4; p++)
            #pragma unroll
            for (int j = 0; j < 4; j++) acc2[p][j] = 0ull;

        #pragma unroll 8
        for (int k = 0; k < DD; k++) {
            // h row-pairs load directly as packed u64 (broadcast across tx)
            ulonglong2 hA = *(const ulonglong2*)&sh_h[k * TM + ty * 8];
            ulonglong2 hB = *(const ulonglong2*)&sh_h[k * TM + ty * 8 + 4];
            u64 hp[4] = {hA.x, hA.y, hB.x, hB.y};
            // A cols: contiguous 16B per thread -> conflict-free LDS.128
            float4 av = *(const float4*)&sh_a[k * TN + tx * 4];
            u64 ap[4] = {pack_ff(av.x, av.x), pack_ff(av.y, av.y),
                         pack_ff(av.z, av.z), pack_ff(av.w, av.w)};
            #pragma unroll
            for (int p = 0; p < 4; p++)
                #pragma unroll
                for (int j = 0; j < 4; j++)
                    acc2[p][j] = ffma2(hp[p], ap[j], acc2[p][j]);
        }

        // ---- unpack (row pairs) + per-row maxes
        float accf[8][4];
        float rmax[8];
        #pragma unroll
        for (int p2 = 0; p2 < 4; p2++)
            #pragma unroll
            for (int j = 0; j < 4; j++)
                unpack_ff(acc2[p2][j], accf[2 * p2][j], accf[2 * p2 + 1][j]);
        #pragma unroll
        for (int p = 0; p < 8; p++) {
            float m = accf[p][0];
            #pragma unroll
            for (int j = 1; j < 4; j++) m = fmaxf(m, accf[p][j]);
            rmax[p] = m;
        }

        // ---- share zbest across the 16 lanes covering the same rows
        #pragma unroll
        for (int p = 0; p < 8; p++) {
            float z = zbest[p];
            #pragma unroll
            for (int o = 8; o > 0; o >>= 1)
                z = fmaxf(z, __shfl_xor_sync(0xffffffffu, z, o, 16));
            zbest[p] = z;
        }

        // ---- bounded-gumbel filter: skip row if even max score + GMAX can't win
        #pragma unroll
        for (int p = 0; p < 8; p++) {
            if (rmax[p] + GMAX >= zbest[p]) {
                unsigned rbase = (unsigned)(gy * TM + ty * 8 + p) * (unsigned)NN;
                #pragma unroll
                for (int j = 0; j < 4; j++) {
                    unsigned c = (unsigned)(cbase + tx * 4 + j);
                    float a = accf[p][j];
                    if (c < (unsigned)NN && a + GMAX >= zbest[p]) {
                        float z = a + gumbel_bits(jax_bits(rbase + c));
                        u64 key = pack_key(z, c);
                        if (key > best[p]) best[p] = key;
                        zbest[p] = fmaxf(zbest[p], z);
                    }
                }
            }
        }
    }

    #pragma unroll
    for (int p = 0; p < 8; p++)
        atomicMax(&g_best[gy * TM + ty * 8 + p], best[p]);
}

// Unpack argmax, cosine similarity, partial reductions (16 blocks x 128 rows).
__global__ __launch_bounds__(128) void k_final(const float* __restrict__ A,
                                               const int* __restrict__ uid,
                                               float* out, int out_size) {
    __shared__ float sbuf[4];
    int tid = threadIdx.x;
    int r = blockIdx.x * 128 + tid;
    unsigned c = ~((unsigned)(g_best[r] & 0xffffffffull));
    if (r < out_size) out[r] = (float)c;
    const float* orig = A + (size_t)uid[2 * r + 1] * DD;
    const float* rep  = A + (size_t)c * DD;
    float dot = 0.f, n1 = 0.f, n2 = 0.f;
    #pragma unroll 4
    for (int k = 0; k < DD; k++) {
        float a = orig[k], b2 = rep[k];
        dot = fmaf(a, b2, dot);
        n1  = fmaf(a, a, n1);
        n2  = fmaf(b2, b2, n2);
    }
    n1 = fmaxf(sqrtf(n1), 1e-6f);
    n2 = fmaxf(sqrtf(n2), 1e-6f);
    float sim = dot / (n1 * n2);
    sim = (sim + 1.f) * 0.5f;
    float d = sim - 0.5f;   // labels = SIM_RATIO = 0.5
    float sl = blockReduceSum(d * d, sbuf, 128);
    float sm = blockReduceSum(sim, sbuf, 128);
    if (tid == 0) {
        g_ps[0][blockIdx.x] = sl;
        g_ps[1][blockIdx.x] = sm;
    }
}

__global__ void k_fin2(float* out, int out_size) {
    if (threadIdx.x == 0 && out_size >= 2050) {
        float sl = 0.f, sm = 0.f;
        for (int i = 0; i < 16; i++) { sl += g_ps[0][i]; sm += g_ps[1][i]; }
        out[2048] = sl * (1.0f / BB);
        out[2049] = sm * (1.0f / BB);
    }
}

// ---------------------------------------------------------------- launcher

extern "C" void kernel_launch(void* const* d_in, const int* in_sizes, int n_in,
                              void* d_out, int out_size) {
    const int*   uid   = (const int*)d_in[0];    // user_item_id [2048,2] int32
    const float* x     = (const float*)d_in[1];  // item_feature [2048,256]
    const float* A     = (const float*)d_in[2];  // all_items [50000,128]
    const float* W     = (const float*)d_in[3];  // W [256,128]
    const float* b     = (const float*)d_in[4];  // b [128]
    const float* gamma = (const float*)d_in[5];  // gamma [128]
    const float* beta  = (const float*)d_in[6];  // beta [128]
    float* out = (float*)d_out;

    (void)in_sizes; (void)n_in;

    size_t smem_bytes = (size_t)(DD * TM + DD * TN) * sizeof(float);  // 96 KB
    cudaFuncSetAttribute(k_score, cudaFuncAttributeMaxDynamicSharedMemorySize,
                         (int)smem_bytes);

    int initN = out_size > BB ? out_size : BB;
    k_init<<<(initN + 255) / 256, 256>>>(out, out_size);
    k_mlp<<<BB / 16, 128>>>(x, W, b);
    k_bn<<<DD, 256>>>(gamma, beta);
    dim3 grid(SPLITS, 16);
    k_score<<<grid, 256, smem_bytes>>>(A);
    k_final<<<16, 128>>>(A, uid, out, out_size);
    k_fin2<<<1, 32>>>(out, out_size);
}